// round 3
// baseline (speedup 1.0000x reference)
#include <cuda_runtime.h>

// ---------------- problem constants ----------------
// x: (32, 128, 128, 80) fp32; C=80, NH=8, DH=10, WIN=GRID=8 -> 64-token windows
// windows per stage: 32 * 16 * 16 = 8192 ; tokens total 524288

#define TOK_TOTAL (32*128*128)

__device__ float g_buf1[(size_t)TOK_TOTAL * 80];
__device__ float g_buf2[(size_t)TOK_TOTAL * 80];

constexpr int XN_S  = 81;   // padded row stride (odd -> conflict-free)
constexpr int QKV_S = 242;  // even (float2-aligned), 242 % 32 = 18 -> conflict-free for lane patterns used
constexpr int O_S   = 81;

constexpr int ATTN_SMEM_FLOATS = 19200 + 240 + 6400 + 80 + 64*XN_S + 64*QKV_S + 64*O_S; // 51776
constexpr int MLP_SMEM_FLOATS  = 25600 + 80 + 80 + 64*XN_S + 64*321;                    // 51488

// =====================================================================
// Fused window attention: l2norm -> QKV -> softmax-attn -> proj -> +res
// One CTA per 64-token window, 256 threads.
// =====================================================================
template<bool IS_GRID>
__global__ void __launch_bounds__(256, 1)
attn_kernel(const float* __restrict__ x, float* __restrict__ y,
            const float* __restrict__ wqkv, const float* __restrict__ bqkv,
            const float* __restrict__ wproj, const float* __restrict__ bproj)
{
    extern __shared__ float sm[];
    float* sWqkv  = sm;                 // 80*240
    float* sBqkv  = sWqkv + 19200;      // 240
    float* sWproj = sBqkv + 240;        // 80*80
    float* sBproj = sWproj + 6400;      // 80
    float* sXN    = sBproj + 80;        // 64 x XN_S
    float* sQKV   = sXN + 64*XN_S;      // 64 x QKV_S
    float* sO     = sQKV + 64*QKV_S;    // 64 x O_S

    const int tid = threadIdx.x;

    // ---- weights -> smem (vectorized) ----
    {
        const float4* src = reinterpret_cast<const float4*>(wqkv);
        float4* dst = reinterpret_cast<float4*>(sWqkv);
        for (int i = tid; i < 4800; i += 256) dst[i] = src[i];
        src = reinterpret_cast<const float4*>(wproj);
        dst = reinterpret_cast<float4*>(sWproj);
        for (int i = tid; i < 1600; i += 256) dst[i] = src[i];
        if (tid < 240) sBqkv[tid] = bqkv[tid];
        if (tid < 80)  sBproj[tid] = bproj[tid];
    }

    // ---- window -> pixel mapping ----
    const int wIdx = blockIdx.x;
    const int bb  = wIdx >> 8;      // batch
    const int rem = wIdx & 255;
    const int wh  = rem >> 4, ww = rem & 15;

    // ---- load + l2norm (4 threads per token) ----
    {
        const int t = tid >> 2, lg = tid & 3;
        const int ti = t >> 3, tj = t & 7;
        int pr, pc;
        if (IS_GRID) { pr = ti*16 + wh; pc = tj*16 + ww; }
        else         { pr = wh*8 + ti;  pc = ww*8 + tj;  }
        const long pix = ((long)bb*128 + pr)*128 + pc;
        const float4* xr = reinterpret_cast<const float4*>(x + pix*80) + lg*5;
        float v[20]; float ss = 0.f;
        #pragma unroll
        for (int u = 0; u < 5; u++) {
            float4 f = xr[u];
            v[4*u+0]=f.x; v[4*u+1]=f.y; v[4*u+2]=f.z; v[4*u+3]=f.w;
            ss += f.x*f.x + f.y*f.y + f.z*f.z + f.w*f.w;
        }
        ss += __shfl_xor_sync(0xffffffffu, ss, 1);
        ss += __shfl_xor_sync(0xffffffffu, ss, 2);
        const float inv = rsqrtf(fmaxf(ss, 1e-24f));  // == 1/max(sqrt(ss),1e-12)
        #pragma unroll
        for (int u = 0; u < 20; u++) sXN[t*XN_S + lg*20 + u] = v[u]*inv;
    }
    __syncthreads();

    // ---- QKV GEMM: [64x80] @ [80x240] + bias ----
    {
        const int a = tid & 15, bc = tid >> 4;   // tokens a+16r, cols bc+16j
        float acc[4][15];
        #pragma unroll
        for (int j = 0; j < 15; j++) {
            float bv = sBqkv[bc + 16*j];
            acc[0][j]=bv; acc[1][j]=bv; acc[2][j]=bv; acc[3][j]=bv;
        }
        for (int k = 0; k < 80; k++) {
            float x0 = sXN[ a      *XN_S + k];
            float x1 = sXN[(a+16)*XN_S + k];
            float x2 = sXN[(a+32)*XN_S + k];
            float x3 = sXN[(a+48)*XN_S + k];
            const float* wr = sWqkv + k*240 + bc;
            #pragma unroll
            for (int j = 0; j < 15; j++) {
                float wv = wr[16*j];
                acc[0][j] += x0*wv; acc[1][j] += x1*wv;
                acc[2][j] += x2*wv; acc[3][j] += x3*wv;
            }
        }
        #pragma unroll
        for (int r = 0; r < 4; r++)
            #pragma unroll
            for (int j = 0; j < 15; j++)
                sQKV[(a+16*r)*QKV_S + bc + 16*j] = acc[r][j];
    }
    __syncthreads();

    // ---- attention: 512 (head,query) rows, 2 per thread ----
    // layout per token row: n = h*30 + {0:q,10:k,20:v} + d
    for (int rr = 0; rr < 2; rr++) {
        const int row = tid + rr*256;
        const int h = row >> 6, q = row & 63;
        const float* qp = sQKV + q*QKV_S + h*30;
        float qv[10];
        #pragma unroll
        for (int d = 0; d < 10; d++) qv[d] = qp[d];

        float s[64]; float mx = -1e30f;
        #pragma unroll
        for (int t2 = 0; t2 < 64; t2++) {
            const float2* kp = reinterpret_cast<const float2*>(sQKV + t2*QKV_S + h*30 + 10);
            float acc = 0.f;
            #pragma unroll
            for (int u = 0; u < 5; u++) {
                float2 kk = kp[u];
                acc += qv[2*u]*kk.x + qv[2*u+1]*kk.y;
            }
            acc *= 0.31622776601683794f;   // DH^-0.5
            s[t2] = acc;
            mx = fmaxf(mx, acc);
        }
        float ssum = 0.f;
        #pragma unroll
        for (int t2 = 0; t2 < 64; t2++) {
            float e = __expf(s[t2] - mx);
            s[t2] = e; ssum += e;
        }
        const float invs = 1.0f / ssum;

        float o[10];
        #pragma unroll
        for (int d = 0; d < 10; d++) o[d] = 0.f;
        #pragma unroll
        for (int t2 = 0; t2 < 64; t2++) {
            const float p = s[t2];
            const float2* vp = reinterpret_cast<const float2*>(sQKV + t2*QKV_S + h*30 + 20);
            #pragma unroll
            for (int u = 0; u < 5; u++) {
                float2 vv = vp[u];
                o[2*u]   += p*vv.x;
                o[2*u+1] += p*vv.y;
            }
        }
        #pragma unroll
        for (int d = 0; d < 10; d++) sO[q*O_S + h*10 + d] = o[d]*invs;
    }
    __syncthreads();

    // ---- proj + residual (accumulate into sXN in place) ----
    {
        const int a = tid & 15, bc = tid >> 4;   // cols c = bc*5+j
        float acc[4][5];
        #pragma unroll
        for (int j = 0; j < 5; j++) {
            float bv = sBproj[bc*5 + j];
            acc[0][j]=bv; acc[1][j]=bv; acc[2][j]=bv; acc[3][j]=bv;
        }
        for (int k = 0; k < 80; k++) {
            float o0 = sO[ a      *O_S + k];
            float o1 = sO[(a+16)*O_S + k];
            float o2 = sO[(a+32)*O_S + k];
            float o3 = sO[(a+48)*O_S + k];
            const float* wr = sWproj + k*80 + bc*5;
            #pragma unroll
            for (int j = 0; j < 5; j++) {
                float wv = wr[j];
                acc[0][j] += o0*wv; acc[1][j] += o1*wv;
                acc[2][j] += o2*wv; acc[3][j] += o3*wv;
            }
        }
        #pragma unroll
        for (int r = 0; r < 4; r++) {
            const int tt = a + 16*r;
            #pragma unroll
            for (int j = 0; j < 5; j++)
                sXN[tt*XN_S + bc*5 + j] += acc[r][j];   // owner-exclusive element
        }
    }
    __syncthreads();

    // ---- coalesced store ----
    {
        const int t = tid >> 2, lg = tid & 3;
        const int ti = t >> 3, tj = t & 7;
        int pr, pc;
        if (IS_GRID) { pr = ti*16 + wh; pc = tj*16 + ww; }
        else         { pr = wh*8 + ti;  pc = ww*8 + tj;  }
        const long pix = ((long)bb*128 + pr)*128 + pc;
        float4* yr = reinterpret_cast<float4*>(y + pix*80) + lg*5;
        #pragma unroll
        for (int u = 0; u < 5; u++) {
            float4 f;
            f.x = sXN[t*XN_S + lg*20 + 4*u + 0];
            f.y = sXN[t*XN_S + lg*20 + 4*u + 1];
            f.z = sXN[t*XN_S + lg*20 + 4*u + 2];
            f.w = sXN[t*XN_S + lg*20 + 4*u + 3];
            yr[u] = f;
        }
    }
}

// =====================================================================
// Fused MLP: l2norm -> relu(x@w1) -> (relu?)(h@w2+b2) -> x + h*gamma
// One CTA per 64 contiguous tokens, 256 threads.
// =====================================================================
template<bool RELU2>
__global__ void __launch_bounds__(256, 1)
mlp_kernel(const float* __restrict__ xin, float* __restrict__ xout,
           const float* __restrict__ w1, const float* __restrict__ w2,
           const float* __restrict__ b2, const float* __restrict__ gamma)
{
    extern __shared__ float sm[];
    float* sW  = sm;            // 25600 (w1, later overwritten by w2)
    float* sB2 = sW + 25600;    // 80
    float* sG  = sB2 + 80;      // 80
    float* sXN = sG + 80;       // 64 x XN_S
    float* sH  = sXN + 64*XN_S; // 64 x 321

    const int tid = threadIdx.x;
    const long tokBase = (long)blockIdx.x * 64;

    // ---- load + l2norm ----
    {
        const int t = tid >> 2, lg = tid & 3;
        const float4* xr = reinterpret_cast<const float4*>(xin + (tokBase + t)*80) + lg*5;
        float v[20]; float ssq = 0.f;
        #pragma unroll
        for (int u = 0; u < 5; u++) {
            float4 f = xr[u];
            v[4*u]=f.x; v[4*u+1]=f.y; v[4*u+2]=f.z; v[4*u+3]=f.w;
            ssq += f.x*f.x + f.y*f.y + f.z*f.z + f.w*f.w;
        }
        ssq += __shfl_xor_sync(0xffffffffu, ssq, 1);
        ssq += __shfl_xor_sync(0xffffffffu, ssq, 2);
        const float inv = rsqrtf(fmaxf(ssq, 1e-24f));
        #pragma unroll
        for (int u = 0; u < 20; u++) sXN[t*XN_S + lg*20 + u] = v[u]*inv;
    }
    // ---- W1 + b2 + gamma -> smem ----
    {
        const float4* src = reinterpret_cast<const float4*>(w1);
        float4* dst = reinterpret_cast<float4*>(sW);
        for (int i = tid; i < 6400; i += 256) dst[i] = src[i];
        if (tid < 80) sB2[tid] = b2[tid];
        if (tid >= 128 && tid < 208) sG[tid-128] = gamma[tid-128];
    }
    __syncthreads();

    const int a = tid & 15, bc = tid >> 4;

    // ---- phase 1: H = relu(XN @ W1), cols bc*20..bc*20+19 ----
    {
        float acc[4][20];
        #pragma unroll
        for (int r = 0; r < 4; r++)
            #pragma unroll
            for (int j = 0; j < 20; j++) acc[r][j] = 0.f;
        for (int k = 0; k < 80; k++) {
            float x0 = sXN[ a      *XN_S + k];
            float x1 = sXN[(a+16)*XN_S + k];
            float x2 = sXN[(a+32)*XN_S + k];
            float x3 = sXN[(a+48)*XN_S + k];
            const float4* wr = reinterpret_cast<const float4*>(sW + k*320 + bc*20);
            #pragma unroll
            for (int u = 0; u < 5; u++) {
                float4 wv = wr[u];
                acc[0][4*u]+=x0*wv.x; acc[0][4*u+1]+=x0*wv.y; acc[0][4*u+2]+=x0*wv.z; acc[0][4*u+3]+=x0*wv.w;
                acc[1][4*u]+=x1*wv.x; acc[1][4*u+1]+=x1*wv.y; acc[1][4*u+2]+=x1*wv.z; acc[1][4*u+3]+=x1*wv.w;
                acc[2][4*u]+=x2*wv.x; acc[2][4*u+1]+=x2*wv.y; acc[2][4*u+2]+=x2*wv.z; acc[2][4*u+3]+=x2*wv.w;
                acc[3][4*u]+=x3*wv.x; acc[3][4*u+1]+=x3*wv.y; acc[3][4*u+2]+=x3*wv.z; acc[3][4*u+3]+=x3*wv.w;
            }
        }
        #pragma unroll
        for (int r = 0; r < 4; r++)
            #pragma unroll
            for (int j = 0; j < 20; j++)
                sH[(a+16*r)*321 + bc*20 + j] = fmaxf(acc[r][j], 0.f);
    }
    __syncthreads();

    // ---- W2 -> smem (overwrite W1) ----
    {
        const float4* src = reinterpret_cast<const float4*>(w2);
        float4* dst = reinterpret_cast<float4*>(sW);
        for (int i = tid; i < 6400; i += 256) dst[i] = src[i];
    }
    __syncthreads();

    // ---- phase 2: out = XN + act(H @ W2 + b2) * gamma ----
    {
        float acc[4][5];
        #pragma unroll
        for (int j = 0; j < 5; j++) {
            float bv = sB2[bc*5 + j];
            acc[0][j]=bv; acc[1][j]=bv; acc[2][j]=bv; acc[3][j]=bv;
        }
        for (int k = 0; k < 320; k++) {
            float h0 = sH[ a      *321 + k];
            float h1 = sH[(a+16)*321 + k];
            float h2 = sH[(a+32)*321 + k];
            float h3 = sH[(a+48)*321 + k];
            const float* wr = sW + k*80 + bc*5;
            #pragma unroll
            for (int j = 0; j < 5; j++) {
                float wv = wr[j];
                acc[0][j] += h0*wv; acc[1][j] += h1*wv;
                acc[2][j] += h2*wv; acc[3][j] += h3*wv;
            }
        }
        #pragma unroll
        for (int r = 0; r < 4; r++) {
            const int tt = a + 16*r;
            #pragma unroll
            for (int j = 0; j < 5; j++) {
                float hv = acc[r][j];
                if (RELU2) hv = fmaxf(hv, 0.f);
                sXN[tt*XN_S + bc*5 + j] += hv * sG[bc*5 + j];  // owner-exclusive
            }
        }
    }
    __syncthreads();

    // ---- coalesced store ----
    {
        const int t = tid >> 2, lg = tid & 3;
        float4* yr = reinterpret_cast<float4*>(xout + (tokBase + t)*80) + lg*5;
        #pragma unroll
        for (int u = 0; u < 5; u++) {
            float4 f;
            f.x = sXN[t*XN_S + lg*20 + 4*u + 0];
            f.y = sXN[t*XN_S + lg*20 + 4*u + 1];
            f.z = sXN[t*XN_S + lg*20 + 4*u + 2];
            f.w = sXN[t*XN_S + lg*20 + 4*u + 3];
            yr[u] = f;
        }
    }
}

// =====================================================================
extern "C" void kernel_launch(void* const* d_in, const int* in_sizes, int n_in,
                              void* d_out, int out_size)
{
    const float* x       = (const float*)d_in[0];
    const float* bw_qkv  = (const float*)d_in[1];
    const float* bb_qkv  = (const float*)d_in[2];
    const float* bw_proj = (const float*)d_in[3];
    const float* bb_proj = (const float*)d_in[4];
    const float* b_gamma = (const float*)d_in[5];
    const float* bw_mlp1 = (const float*)d_in[6];
    const float* bw_mlp2 = (const float*)d_in[7];
    const float* bb_mlp2 = (const float*)d_in[8];
    const float* gw_qkv  = (const float*)d_in[9];
    const float* gb_qkv  = (const float*)d_in[10];
    const float* gw_proj = (const float*)d_in[11];
    const float* gb_proj = (const float*)d_in[12];
    const float* g_gamma = (const float*)d_in[13];
    const float* gw_mlp1 = (const float*)d_in[14];
    const float* gw_mlp2 = (const float*)d_in[15];
    const float* gb_mlp2 = (const float*)d_in[16];
    float* out = (float*)d_out;

    float *buf1 = nullptr, *buf2 = nullptr;
    cudaGetSymbolAddress((void**)&buf1, g_buf1);
    cudaGetSymbolAddress((void**)&buf2, g_buf2);

    const size_t smA = ATTN_SMEM_FLOATS * sizeof(float);   // 207,104 B
    const size_t smM = MLP_SMEM_FLOATS  * sizeof(float);   // 205,952 B
    cudaFuncSetAttribute(attn_kernel<false>, cudaFuncAttributeMaxDynamicSharedMemorySize, (int)smA);
    cudaFuncSetAttribute(attn_kernel<true>,  cudaFuncAttributeMaxDynamicSharedMemorySize, (int)smA);
    cudaFuncSetAttribute(mlp_kernel<true>,   cudaFuncAttributeMaxDynamicSharedMemorySize, (int)smM);
    cudaFuncSetAttribute(mlp_kernel<false>,  cudaFuncAttributeMaxDynamicSharedMemorySize, (int)smM);

    const int NWIN = 8192;           // windows per stage
    const int NTILE = TOK_TOTAL/64;  // 8192 MLP tiles

    // stage 1: block SA
    attn_kernel<false><<<NWIN, 256, smA>>>(x,    buf1, bw_qkv, bb_qkv, bw_proj, bb_proj);
    mlp_kernel<true>  <<<NTILE, 256, smM>>>(buf1, buf2, bw_mlp1, bw_mlp2, bb_mlp2, b_gamma);
    // stage 2: grid SA
    attn_kernel<true> <<<NWIN, 256, smA>>>(buf2, buf1, gw_qkv, gb_qkv, gw_proj, gb_proj);
    mlp_kernel<false> <<<NTILE, 256, smM>>>(buf1, out, gw_mlp1, gw_mlp2, gb_mlp2, g_gamma);
}

// round 4
// speedup vs baseline: 1.7143x; 1.7143x over previous
#include <cuda_runtime.h>
#include <cuda_bf16.h>

// ---------------- problem constants ----------------
// x: (32, 128, 128, 80) fp32; C=80, NH=8, DH=10, WIN=GRID=8 -> 64-token windows
// windows per stage: 32 * 16 * 16 = 8192 ; tokens total 524288

#define TOK_TOTAL (32*128*128)

__device__ float g_buf1[(size_t)TOK_TOTAL * 80];
__device__ float g_buf2[(size_t)TOK_TOTAL * 80];

constexpr int XN_S  = 81;   // padded row stride (odd -> conflict-free)
constexpr int QKV_S = 242;  // even (float2-aligned), conflict-free for lane patterns used
constexpr int O_S   = 81;

constexpr int ATTN_SMEM_FLOATS = 19200 + 240 + 6400 + 80 + 64*XN_S + 64*QKV_S + 64*O_S; // 51776

// ---------------- bf16 mma helpers ----------------
__device__ __forceinline__ unsigned pack2(float lo, float hi) {
    __nv_bfloat162 t = __floats2bfloat162_rn(lo, hi);
    return *reinterpret_cast<unsigned*>(&t);
}

__device__ __forceinline__ void mma_bf16(float* c, const unsigned* a, unsigned b0, unsigned b1) {
    asm volatile(
        "mma.sync.aligned.m16n8k16.row.col.f32.bf16.bf16.f32 "
        "{%0,%1,%2,%3}, {%4,%5,%6,%7}, {%8,%9}, {%0,%1,%2,%3};\n"
        : "+f"(c[0]), "+f"(c[1]), "+f"(c[2]), "+f"(c[3])
        : "r"(a[0]), "r"(a[1]), "r"(a[2]), "r"(a[3]), "r"(b0), "r"(b1));
}

// =====================================================================
// Fused window attention: l2norm -> QKV -> softmax-attn -> proj -> +res
// One CTA per 64-token window, 256 threads.  (unchanged from passing R2)
// =====================================================================
template<bool IS_GRID>
__global__ void __launch_bounds__(256, 1)
attn_kernel(const float* __restrict__ x, float* __restrict__ y,
            const float* __restrict__ wqkv, const float* __restrict__ bqkv,
            const float* __restrict__ wproj, const float* __restrict__ bproj)
{
    extern __shared__ float sm[];
    float* sWqkv  = sm;                 // 80*240
    float* sBqkv  = sWqkv + 19200;      // 240
    float* sWproj = sBqkv + 240;        // 80*80
    float* sBproj = sWproj + 6400;      // 80
    float* sXN    = sBproj + 80;        // 64 x XN_S
    float* sQKV   = sXN + 64*XN_S;      // 64 x QKV_S
    float* sO     = sQKV + 64*QKV_S;    // 64 x O_S

    const int tid = threadIdx.x;

    // ---- weights -> smem (vectorized) ----
    {
        const float4* src = reinterpret_cast<const float4*>(wqkv);
        float4* dst = reinterpret_cast<float4*>(sWqkv);
        for (int i = tid; i < 4800; i += 256) dst[i] = src[i];
        src = reinterpret_cast<const float4*>(wproj);
        dst = reinterpret_cast<float4*>(sWproj);
        for (int i = tid; i < 1600; i += 256) dst[i] = src[i];
        if (tid < 240) sBqkv[tid] = bqkv[tid];
        if (tid < 80)  sBproj[tid] = bproj[tid];
    }

    // ---- window -> pixel mapping ----
    const int wIdx = blockIdx.x;
    const int bb  = wIdx >> 8;      // batch
    const int rem = wIdx & 255;
    const int wh  = rem >> 4, ww = rem & 15;

    // ---- load + l2norm (4 threads per token) ----
    {
        const int t = tid >> 2, lg = tid & 3;
        const int ti = t >> 3, tj = t & 7;
        int pr, pc;
        if (IS_GRID) { pr = ti*16 + wh; pc = tj*16 + ww; }
        else         { pr = wh*8 + ti;  pc = ww*8 + tj;  }
        const long pix = ((long)bb*128 + pr)*128 + pc;
        const float4* xr = reinterpret_cast<const float4*>(x + pix*80) + lg*5;
        float v[20]; float ss = 0.f;
        #pragma unroll
        for (int u = 0; u < 5; u++) {
            float4 f = xr[u];
            v[4*u+0]=f.x; v[4*u+1]=f.y; v[4*u+2]=f.z; v[4*u+3]=f.w;
            ss += f.x*f.x + f.y*f.y + f.z*f.z + f.w*f.w;
        }
        ss += __shfl_xor_sync(0xffffffffu, ss, 1);
        ss += __shfl_xor_sync(0xffffffffu, ss, 2);
        const float inv = rsqrtf(fmaxf(ss, 1e-24f));  // == 1/max(sqrt(ss),1e-12)
        #pragma unroll
        for (int u = 0; u < 20; u++) sXN[t*XN_S + lg*20 + u] = v[u]*inv;
    }
    __syncthreads();

    // ---- QKV GEMM: [64x80] @ [80x240] + bias ----
    {
        const int a = tid & 15, bc = tid >> 4;   // tokens a+16r, cols bc+16j
        float acc[4][15];
        #pragma unroll
        for (int j = 0; j < 15; j++) {
            float bv = sBqkv[bc + 16*j];
            acc[0][j]=bv; acc[1][j]=bv; acc[2][j]=bv; acc[3][j]=bv;
        }
        for (int k = 0; k < 80; k++) {
            float x0 = sXN[ a      *XN_S + k];
            float x1 = sXN[(a+16)*XN_S + k];
            float x2 = sXN[(a+32)*XN_S + k];
            float x3 = sXN[(a+48)*XN_S + k];
            const float* wr = sWqkv + k*240 + bc;
            #pragma unroll
            for (int j = 0; j < 15; j++) {
                float wv = wr[16*j];
                acc[0][j] += x0*wv; acc[1][j] += x1*wv;
                acc[2][j] += x2*wv; acc[3][j] += x3*wv;
            }
        }
        #pragma unroll
        for (int r = 0; r < 4; r++)
            #pragma unroll
            for (int j = 0; j < 15; j++)
                sQKV[(a+16*r)*QKV_S + bc + 16*j] = acc[r][j];
    }
    __syncthreads();

    // ---- attention: 512 (head,query) rows, 2 per thread ----
    // layout per token row: n = h*30 + {0:q,10:k,20:v} + d
    for (int rr = 0; rr < 2; rr++) {
        const int row = tid + rr*256;
        const int h = row >> 6, q = row & 63;
        const float* qp = sQKV + q*QKV_S + h*30;
        float qv[10];
        #pragma unroll
        for (int d = 0; d < 10; d++) qv[d] = qp[d];

        float s[64]; float mx = -1e30f;
        #pragma unroll
        for (int t2 = 0; t2 < 64; t2++) {
            const float2* kp = reinterpret_cast<const float2*>(sQKV + t2*QKV_S + h*30 + 10);
            float acc = 0.f;
            #pragma unroll
            for (int u = 0; u < 5; u++) {
                float2 kk = kp[u];
                acc += qv[2*u]*kk.x + qv[2*u+1]*kk.y;
            }
            acc *= 0.31622776601683794f;   // DH^-0.5
            s[t2] = acc;
            mx = fmaxf(mx, acc);
        }
        float ssum = 0.f;
        #pragma unroll
        for (int t2 = 0; t2 < 64; t2++) {
            float e = __expf(s[t2] - mx);
            s[t2] = e; ssum += e;
        }
        const float invs = 1.0f / ssum;

        float o[10];
        #pragma unroll
        for (int d = 0; d < 10; d++) o[d] = 0.f;
        #pragma unroll
        for (int t2 = 0; t2 < 64; t2++) {
            const float p = s[t2];
            const float2* vp = reinterpret_cast<const float2*>(sQKV + t2*QKV_S + h*30 + 20);
            #pragma unroll
            for (int u = 0; u < 5; u++) {
                float2 vv = vp[u];
                o[2*u]   += p*vv.x;
                o[2*u+1] += p*vv.y;
            }
        }
        #pragma unroll
        for (int d = 0; d < 10; d++) sO[q*O_S + h*10 + d] = o[d]*invs;
    }
    __syncthreads();

    // ---- proj + residual (accumulate into sXN in place) ----
    {
        const int a = tid & 15, bc = tid >> 4;   // cols c = bc*5+j
        float acc[4][5];
        #pragma unroll
        for (int j = 0; j < 5; j++) {
            float bv = sBproj[bc*5 + j];
            acc[0][j]=bv; acc[1][j]=bv; acc[2][j]=bv; acc[3][j]=bv;
        }
        for (int k = 0; k < 80; k++) {
            float o0 = sO[ a      *O_S + k];
            float o1 = sO[(a+16)*O_S + k];
            float o2 = sO[(a+32)*O_S + k];
            float o3 = sO[(a+48)*O_S + k];
            const float* wr = sWproj + k*80 + bc*5;
            #pragma unroll
            for (int j = 0; j < 5; j++) {
                float wv = wr[j];
                acc[0][j] += o0*wv; acc[1][j] += o1*wv;
                acc[2][j] += o2*wv; acc[3][j] += o3*wv;
            }
        }
        #pragma unroll
        for (int r = 0; r < 4; r++) {
            const int tt = a + 16*r;
            #pragma unroll
            for (int j = 0; j < 5; j++)
                sXN[tt*XN_S + bc*5 + j] += acc[r][j];   // owner-exclusive element
        }
    }
    __syncthreads();

    // ---- coalesced store ----
    {
        const int t = tid >> 2, lg = tid & 3;
        const int ti = t >> 3, tj = t & 7;
        int pr, pc;
        if (IS_GRID) { pr = ti*16 + wh; pc = tj*16 + ww; }
        else         { pr = wh*8 + ti;  pc = ww*8 + tj;  }
        const long pix = ((long)bb*128 + pr)*128 + pc;
        float4* yr = reinterpret_cast<float4*>(y + pix*80) + lg*5;
        #pragma unroll
        for (int u = 0; u < 5; u++) {
            float4 f;
            f.x = sXN[t*XN_S + lg*20 + 4*u + 0];
            f.y = sXN[t*XN_S + lg*20 + 4*u + 1];
            f.z = sXN[t*XN_S + lg*20 + 4*u + 2];
            f.w = sXN[t*XN_S + lg*20 + 4*u + 3];
            yr[u] = f;
        }
    }
}

// =====================================================================
// Fused MLP via bf16 mma.sync:
//   l2norm -> H=relu(XN@W1) -> out = XN + act(H@W2+b2)*gamma
// Grid: 2048 CTAs x 4 tiles of 64 tokens; weights staged once per CTA
// (transposed bf16) and reused across the 4 tiles.
//
// smem layout (bytes):
//   sW1T  [320 x 88] bf16   @      0   (56320)
//   sW2T  [ 80 x 344] bf16  @  56320   (55040)
//   sXN   [ 64 x 81] f32    @ 111360   (20736)   fp32 residual
//   sXNh  [ 64 x 88] bf16   @ 132096   (11264)   mma A panel
//   sH    [ 64 x 344] bf16  @ 143360   (44032)   (aliased by sOut f32 [64x81])
//   sB2   [80] f32          @ 187392
//   sG    [80] f32          @ 187712
// total 188032 B.  Strides 88/344: stride/2 mod 32 = 12 -> fragment LDS
// across 8 row-groups hits banks {0,12,24,4,16,28,8,20} (conflict-free).
// =====================================================================
constexpr int MLP_SMEM_BYTES = 188032;
constexpr int MLP_TILES_PER_CTA = 4;
constexpr int MLP_NCTA = (TOK_TOTAL/64) / MLP_TILES_PER_CTA;  // 2048

template<bool RELU2>
__global__ void __launch_bounds__(256, 1)
mlp_kernel(const float* __restrict__ xin, float* __restrict__ xout,
           const float* __restrict__ w1, const float* __restrict__ w2,
           const float* __restrict__ b2, const float* __restrict__ gamma)
{
    extern __shared__ float smf[];
    char* smb = reinterpret_cast<char*>(smf);
    __nv_bfloat16* sW1T = reinterpret_cast<__nv_bfloat16*>(smb);            // [n=320][k=88]
    __nv_bfloat16* sW2T = reinterpret_cast<__nv_bfloat16*>(smb + 56320);    // [n=80][k=344]
    float*         sXN  = reinterpret_cast<float*>(smb + 111360);           // [64][81]
    __nv_bfloat16* sXNh = reinterpret_cast<__nv_bfloat16*>(smb + 132096);   // [64][88]
    __nv_bfloat16* sH   = reinterpret_cast<__nv_bfloat16*>(smb + 143360);   // [64][344]
    float*         sOut = reinterpret_cast<float*>(smb + 143360);           // alias: [64][81]
    float*         sB2  = reinterpret_cast<float*>(smb + 187392);
    float*         sG   = reinterpret_cast<float*>(smb + 187712);

    const int tid = threadIdx.x;

    // ---- stage weights once: transpose + convert to bf16 ----
    for (int idx = tid; idx < 25600; idx += 256) {
        { int k = idx / 320, n = idx % 320; sW1T[n*88  + k] = __float2bfloat16(w1[idx]); }
        { int k = idx / 80,  n = idx % 80;  sW2T[n*344 + k] = __float2bfloat16(w2[idx]); }
    }
    if (tid < 80) { sB2[tid] = b2[tid]; sG[tid] = gamma[tid]; }

    const int w    = tid >> 5, lane = tid & 31;
    const int g    = lane >> 2, tq  = lane & 3;   // mma row-group / thread-in-group

    for (int it = 0; it < MLP_TILES_PER_CTA; it++) {
        const long tokBase = ((long)blockIdx.x * MLP_TILES_PER_CTA + it) * 64;

        // ---- load + l2norm (fp32 residual + bf16 A panel) ----
        {
            const int t = tid >> 2, lg = tid & 3;
            const float4* xr = reinterpret_cast<const float4*>(xin + (tokBase + t)*80) + lg*5;
            float v[20]; float ssq = 0.f;
            #pragma unroll
            for (int u = 0; u < 5; u++) {
                float4 f = xr[u];
                v[4*u]=f.x; v[4*u+1]=f.y; v[4*u+2]=f.z; v[4*u+3]=f.w;
                ssq += f.x*f.x + f.y*f.y + f.z*f.z + f.w*f.w;
            }
            ssq += __shfl_xor_sync(0xffffffffu, ssq, 1);
            ssq += __shfl_xor_sync(0xffffffffu, ssq, 2);
            const float inv = rsqrtf(fmaxf(ssq, 1e-24f));
            float* xn = sXN + t*81 + lg*20;
            unsigned* xh = reinterpret_cast<unsigned*>(sXNh + t*88 + lg*20);
            #pragma unroll
            for (int u = 0; u < 20; u++) { v[u] *= inv; xn[u] = v[u]; }
            #pragma unroll
            for (int u = 0; u < 10; u++) xh[u] = pack2(v[2*u], v[2*u+1]);
        }
        __syncthreads();   // also covers weight staging before first tile

        // ---- GEMM1: H[64,320] = relu(XNh[64,80] @ W1[80,320]) ----
        {
            const int mt0   = (w & 1) * 2;       // m-tiles {mt0, mt0+1}
            const int nbase = (w >> 1) * 10;     // n-tiles nbase..nbase+9
            float acc[2][10][4];
            #pragma unroll
            for (int mi = 0; mi < 2; mi++)
                #pragma unroll
                for (int j = 0; j < 10; j++)
                    #pragma unroll
                    for (int e = 0; e < 4; e++) acc[mi][j][e] = 0.f;

            #pragma unroll
            for (int ks = 0; ks < 5; ks++) {
                unsigned a[2][4];
                #pragma unroll
                for (int mi = 0; mi < 2; mi++) {
                    const __nv_bfloat16* ap = sXNh + ((mt0+mi)*16 + g)*88 + ks*16;
                    a[mi][0] = *reinterpret_cast<const unsigned*>(ap + 2*tq);
                    a[mi][1] = *reinterpret_cast<const unsigned*>(ap + 8*88 + 2*tq);
                    a[mi][2] = *reinterpret_cast<const unsigned*>(ap + 8 + 2*tq);
                    a[mi][3] = *reinterpret_cast<const unsigned*>(ap + 8*88 + 8 + 2*tq);
                }
                #pragma unroll
                for (int j = 0; j < 10; j++) {
                    const __nv_bfloat16* bp = sW1T + ((nbase+j)*8 + g)*88 + ks*16;
                    unsigned b0 = *reinterpret_cast<const unsigned*>(bp + 2*tq);
                    unsigned b1 = *reinterpret_cast<const unsigned*>(bp + 8 + 2*tq);
                    mma_bf16(acc[0][j], a[0], b0, b1);
                    mma_bf16(acc[1][j], a[1], b0, b1);
                }
            }
            // relu -> bf16 -> sH
            #pragma unroll
            for (int mi = 0; mi < 2; mi++) {
                const int r0 = (mt0+mi)*16 + g;
                #pragma unroll
                for (int j = 0; j < 10; j++) {
                    const int c = (nbase+j)*8 + 2*tq;
                    *reinterpret_cast<unsigned*>(sH + r0*344 + c) =
                        pack2(fmaxf(acc[mi][j][0], 0.f), fmaxf(acc[mi][j][1], 0.f));
                    *reinterpret_cast<unsigned*>(sH + (r0+8)*344 + c) =
                        pack2(fmaxf(acc[mi][j][2], 0.f), fmaxf(acc[mi][j][3], 0.f));
                }
            }
        }
        __syncthreads();

        // ---- GEMM2: D[64,80] = H[64,320] @ W2[320,80] ----
        {
            const int mt = w & 3;
            const int nb = (w >> 2) * 5;        // n-tiles nb..nb+4
            float acc2[5][4];
            #pragma unroll
            for (int j = 0; j < 5; j++)
                #pragma unroll
                for (int e = 0; e < 4; e++) acc2[j][e] = 0.f;

            #pragma unroll
            for (int ks = 0; ks < 20; ks++) {
                unsigned a[4];
                const __nv_bfloat16* ap = sH + (mt*16 + g)*344 + ks*16;
                a[0] = *reinterpret_cast<const unsigned*>(ap + 2*tq);
                a[1] = *reinterpret_cast<const unsigned*>(ap + 8*344 + 2*tq);
                a[2] = *reinterpret_cast<const unsigned*>(ap + 8 + 2*tq);
                a[3] = *reinterpret_cast<const unsigned*>(ap + 8*344 + 8 + 2*tq);
                #pragma unroll
                for (int j = 0; j < 5; j++) {
                    const __nv_bfloat16* bp = sW2T + ((nb+j)*8 + g)*344 + ks*16;
                    unsigned b0 = *reinterpret_cast<const unsigned*>(bp + 2*tq);
                    unsigned b1 = *reinterpret_cast<const unsigned*>(bp + 8 + 2*tq);
                    mma_bf16(acc2[j], a, b0, b1);
                }
            }
            __syncthreads();   // all warps done reading sH before sOut overwrites it
            const int r0 = mt*16 + g;
            #pragma unroll
            for (int j = 0; j < 5; j++) {
                const int c = (nb+j)*8 + 2*tq;
                sOut[r0*81 + c]       = acc2[j][0];
                sOut[r0*81 + c + 1]   = acc2[j][1];
                sOut[(r0+8)*81 + c]     = acc2[j][2];
                sOut[(r0+8)*81 + c + 1] = acc2[j][3];
            }
        }
        __syncthreads();

        // ---- epilogue: out = XN + act(D + b2)*gamma ; coalesced store ----
        {
            const int t = tid >> 2, lg = tid & 3;
            float4* yr = reinterpret_cast<float4*>(xout + (tokBase + t)*80) + lg*5;
            #pragma unroll
            for (int u = 0; u < 5; u++) {
                float f[4];
                #pragma unroll
                for (int e = 0; e < 4; e++) {
                    const int idx = lg*20 + 4*u + e;
                    float hv = sOut[t*81 + idx] + sB2[idx];
                    if (RELU2) hv = fmaxf(hv, 0.f);
                    f[e] = sXN[t*81 + idx] + hv * sG[idx];
                }
                yr[u] = make_float4(f[0], f[1], f[2], f[3]);
            }
        }
        __syncthreads();   // before next tile overwrites sXN / sH
    }
}

// =====================================================================
extern "C" void kernel_launch(void* const* d_in, const int* in_sizes, int n_in,
                              void* d_out, int out_size)
{
    const float* x       = (const float*)d_in[0];
    const float* bw_qkv  = (const float*)d_in[1];
    const float* bb_qkv  = (const float*)d_in[2];
    const float* bw_proj = (const float*)d_in[3];
    const float* bb_proj = (const float*)d_in[4];
    const float* b_gamma = (const float*)d_in[5];
    const float* bw_mlp1 = (const float*)d_in[6];
    const float* bw_mlp2 = (const float*)d_in[7];
    const float* bb_mlp2 = (const float*)d_in[8];
    const float* gw_qkv  = (const float*)d_in[9];
    const float* gb_qkv  = (const float*)d_in[10];
    const float* gw_proj = (const float*)d_in[11];
    const float* gb_proj = (const float*)d_in[12];
    const float* g_gamma = (const float*)d_in[13];
    const float* gw_mlp1 = (const float*)d_in[14];
    const float* gw_mlp2 = (const float*)d_in[15];
    const float* gb_mlp2 = (const float*)d_in[16];
    float* out = (float*)d_out;

    float *buf1 = nullptr, *buf2 = nullptr;
    cudaGetSymbolAddress((void**)&buf1, g_buf1);
    cudaGetSymbolAddress((void**)&buf2, g_buf2);

    const size_t smA = ATTN_SMEM_FLOATS * sizeof(float);   // 207,104 B
    const size_t smM = MLP_SMEM_BYTES;                     // 188,032 B
    cudaFuncSetAttribute(attn_kernel<false>, cudaFuncAttributeMaxDynamicSharedMemorySize, (int)smA);
    cudaFuncSetAttribute(attn_kernel<true>,  cudaFuncAttributeMaxDynamicSharedMemorySize, (int)smA);
    cudaFuncSetAttribute(mlp_kernel<true>,   cudaFuncAttributeMaxDynamicSharedMemorySize, (int)smM);
    cudaFuncSetAttribute(mlp_kernel<false>,  cudaFuncAttributeMaxDynamicSharedMemorySize, (int)smM);

    const int NWIN = 8192;           // windows per stage

    // stage 1: block SA
    attn_kernel<false><<<NWIN, 256, smA>>>(x,    buf1, bw_qkv, bb_qkv, bw_proj, bb_proj);
    mlp_kernel<true>  <<<MLP_NCTA, 256, smM>>>(buf1, buf2, bw_mlp1, bw_mlp2, bb_mlp2, b_gamma);
    // stage 2: grid SA
    attn_kernel<true> <<<NWIN, 256, smA>>>(buf2, buf1, gw_qkv, gb_qkv, gw_proj, gb_proj);
    mlp_kernel<false> <<<MLP_NCTA, 256, smM>>>(buf1, out, gw_mlp1, gw_mlp2, gb_mlp2, g_gamma);
}

// round 5
// speedup vs baseline: 3.3424x; 1.9498x over previous
#include <cuda_runtime.h>
#include <cuda_bf16.h>

// ---------------- problem constants ----------------
// x: (32, 128, 128, 80) fp32; C=80, NH=8, DH=10, WIN=GRID=8 -> 64-token windows
// windows per stage: 32 * 16 * 16 = 8192 ; tokens total 524288

#define TOK_TOTAL (32*128*128)

__device__ float g_buf1[(size_t)TOK_TOTAL * 80];
__device__ float g_buf2[(size_t)TOK_TOTAL * 80];

// ---------------- bf16 mma helpers (fragment conventions validated R3) ----
__device__ __forceinline__ unsigned pack2(float lo, float hi) {
    __nv_bfloat162 t = __floats2bfloat162_rn(lo, hi);
    return *reinterpret_cast<unsigned*>(&t);
}

__device__ __forceinline__ void mma_bf16(float* c, const unsigned* a, unsigned b0, unsigned b1) {
    asm volatile(
        "mma.sync.aligned.m16n8k16.row.col.f32.bf16.bf16.f32 "
        "{%0,%1,%2,%3}, {%4,%5,%6,%7}, {%8,%9}, {%0,%1,%2,%3};\n"
        : "+f"(c[0]), "+f"(c[1]), "+f"(c[2]), "+f"(c[3])
        : "r"(a[0]), "r"(a[1]), "r"(a[2]), "r"(a[3]), "r"(b0), "r"(b1));
}

// =====================================================================
// Fused window attention via bf16 mma:
//   l2norm -> QKV(mma) -> per-head reg-resident softmax-attn(mma) ->
//   proj(mma) + residual -> store
// 256 threads = 8 warps; 1 warp per head in the attention phase.
// 4 windows per CTA; weights staged (transposed bf16) once per CTA.
//
// smem layout (bytes):
//   sWqkvT [240][88] bf16 @      0  (42240)
//   sWprojT [80][88] bf16 @  42240  (14080)
//   sXN    [64][81] f32   @  56320  (20736)  fp32 residual
//   sXNh   [64][88] bf16  @  77056  (11264)  A panel
//   sQ   [8][64][18] bf16 @  88320  (18432)  per-head Q (k padded 10->16, scaled)
//   sK   [8][64][18] bf16 @ 106752  (18432)  per-head K (k padded, zeros)
//   sVT  [8][16][72] bf16 @ 125184  (18432)  per-head V transposed (PV B-op)
//   sO     [64][88] bf16  @ 143616  (11264)  attn out, A panel for proj
//   sBqkv  [240] f32      @ 154880
//   sBproj [80]  f32      @ 155840
// total 156160 B
// =====================================================================
constexpr int ATTN_SMEM_BYTES = 156160;
constexpr int ATTN_TILES_PER_CTA = 4;
constexpr int ATTN_NCTA = 8192 / ATTN_TILES_PER_CTA;   // 2048
constexpr float QK_SCALE = 0.31622776601683794f;       // DH^-0.5

template<bool IS_GRID>
__global__ void __launch_bounds__(256, 1)
attn_kernel(const float* __restrict__ x, float* __restrict__ y,
            const float* __restrict__ wqkv, const float* __restrict__ bqkv,
            const float* __restrict__ wproj, const float* __restrict__ bproj)
{
    extern __shared__ float smf[];
    char* smb = reinterpret_cast<char*>(smf);
    __nv_bfloat16* sWqkvT  = reinterpret_cast<__nv_bfloat16*>(smb);           // [240][88]
    __nv_bfloat16* sWprojT = reinterpret_cast<__nv_bfloat16*>(smb + 42240);   // [80][88]
    float*         sXN     = reinterpret_cast<float*>(smb + 56320);           // [64][81]
    __nv_bfloat16* sXNh    = reinterpret_cast<__nv_bfloat16*>(smb + 77056);   // [64][88]
    __nv_bfloat16* sQ      = reinterpret_cast<__nv_bfloat16*>(smb + 88320);   // [8][64][18]
    __nv_bfloat16* sK      = reinterpret_cast<__nv_bfloat16*>(smb + 106752);  // [8][64][18]
    __nv_bfloat16* sVT     = reinterpret_cast<__nv_bfloat16*>(smb + 125184);  // [8][16][72]
    __nv_bfloat16* sO      = reinterpret_cast<__nv_bfloat16*>(smb + 143616);  // [64][88]
    float*         sBqkv   = reinterpret_cast<float*>(smb + 154880);          // [240]
    float*         sBproj  = reinterpret_cast<float*>(smb + 155840);          // [80]

    const int tid  = threadIdx.x;
    const int w    = tid >> 5, lane = tid & 31;
    const int g    = lane >> 2, tq  = lane & 3;

    // ---- one-time: weights transposed->bf16, biases, pad zeroing ----
    for (int idx = tid; idx < 19200; idx += 256) {
        int k = idx / 240, n = idx % 240;
        sWqkvT[n*88 + k] = __float2bfloat16(wqkv[idx]);
    }
    for (int idx = tid; idx < 6400; idx += 256) {
        int k = idx / 80, n = idx % 80;
        sWprojT[n*88 + k] = __float2bfloat16(wproj[idx]);
    }
    if (tid < 240) sBqkv[tid] = bqkv[tid];
    if (tid < 80)  sBproj[tid] = bproj[tid];
    // zero k-pads d=10..17 of sQ and sK (QKV stores only touch d<10, so
    // these stay zero for all 4 tiles).  8*64 rows * 8 pads = 4096 bf16 each.
    for (int i = tid; i < 2048; i += 256) {          // 2048 u32 = 4096 bf16
        int row = i >> 2, p = i & 3;                  // row 0..511, pad pair p
        unsigned* q = reinterpret_cast<unsigned*>(sQ + row*18 + 10) + p;
        unsigned* k = reinterpret_cast<unsigned*>(sK + row*18 + 10) + p;
        *q = 0u; *k = 0u;
    }

    for (int it = 0; it < ATTN_TILES_PER_CTA; it++) {
        const int wIdx = blockIdx.x * ATTN_TILES_PER_CTA + it;
        const int bb  = wIdx >> 8;
        const int rem = wIdx & 255;
        const int wh  = rem >> 4, ww = rem & 15;

        // ---- load + l2norm: fp32 residual + bf16 A panel ----
        {
            const int t = tid >> 2, lg = tid & 3;
            const int ti = t >> 3, tj = t & 7;
            int pr, pc;
            if (IS_GRID) { pr = ti*16 + wh; pc = tj*16 + ww; }
            else         { pr = wh*8 + ti;  pc = ww*8 + tj;  }
            const long pix = ((long)bb*128 + pr)*128 + pc;
            const float4* xr = reinterpret_cast<const float4*>(x + pix*80) + lg*5;
            float v[20]; float ss = 0.f;
            #pragma unroll
            for (int u = 0; u < 5; u++) {
                float4 f = xr[u];
                v[4*u+0]=f.x; v[4*u+1]=f.y; v[4*u+2]=f.z; v[4*u+3]=f.w;
                ss += f.x*f.x + f.y*f.y + f.z*f.z + f.w*f.w;
            }
            ss += __shfl_xor_sync(0xffffffffu, ss, 1);
            ss += __shfl_xor_sync(0xffffffffu, ss, 2);
            const float inv = rsqrtf(fmaxf(ss, 1e-24f));
            float* xn = sXN + t*81 + lg*20;
            unsigned* xh = reinterpret_cast<unsigned*>(sXNh + t*88 + lg*20);
            #pragma unroll
            for (int u = 0; u < 20; u++) { v[u] *= inv; xn[u] = v[u]; }
            #pragma unroll
            for (int u = 0; u < 10; u++) xh[u] = pack2(v[2*u], v[2*u+1]);
        }
        __syncthreads();   // (covers one-time staging before first tile)

        // ---- QKV GEMM: [64x80]@[80x240], scatter into sQ/sK/sVT ----
        {
            const int mt    = w >> 1;
            const int jbase = (w & 1) * 15;
            float acc[15][4];
            #pragma unroll
            for (int j = 0; j < 15; j++)
                #pragma unroll
                for (int e = 0; e < 4; e++) acc[j][e] = 0.f;

            #pragma unroll
            for (int ks = 0; ks < 5; ks++) {
                unsigned a[4];
                const __nv_bfloat16* ap = sXNh + (mt*16 + g)*88 + ks*16;
                a[0] = *reinterpret_cast<const unsigned*>(ap + 2*tq);
                a[1] = *reinterpret_cast<const unsigned*>(ap + 8*88 + 2*tq);
                a[2] = *reinterpret_cast<const unsigned*>(ap + 2*tq + 8);
                a[3] = *reinterpret_cast<const unsigned*>(ap + 8*88 + 2*tq + 8);
                #pragma unroll
                for (int j = 0; j < 15; j++) {
                    const __nv_bfloat16* bp = sWqkvT + ((jbase+j)*8 + g)*88 + ks*16;
                    unsigned b0 = *reinterpret_cast<const unsigned*>(bp + 2*tq);
                    unsigned b1 = *reinterpret_cast<const unsigned*>(bp + 2*tq + 8);
                    mma_bf16(acc[j], a, b0, b1);
                }
            }
            const int rowA = mt*16 + g;
            #pragma unroll
            for (int j = 0; j < 15; j++) {
                #pragma unroll
                for (int e = 0; e < 2; e++) {
                    const int col = (jbase+j)*8 + 2*tq + e;
                    const int h = col / 30;
                    const int r = col - h*30;
                    const int d = (r >= 20) ? r - 20 : (r >= 10 ? r - 10 : r);
                    const float bias = sBqkv[col];
                    float vA = acc[j][e]   + bias;
                    float vB = acc[j][2+e] + bias;
                    if (r < 10) {          // Q (scaled)
                        sQ[h*1152 + rowA*18 + d]     = __float2bfloat16(vA * QK_SCALE);
                        sQ[h*1152 + (rowA+8)*18 + d] = __float2bfloat16(vB * QK_SCALE);
                    } else if (r < 20) {   // K
                        sK[h*1152 + rowA*18 + d]     = __float2bfloat16(vA);
                        sK[h*1152 + (rowA+8)*18 + d] = __float2bfloat16(vB);
                    } else {               // V transposed
                        sVT[h*1152 + d*72 + rowA]     = __float2bfloat16(vA);
                        sVT[h*1152 + d*72 + rowA + 8] = __float2bfloat16(vB);
                    }
                }
            }
        }
        __syncthreads();

        // ---- attention: warp w == head w, register-resident ----
        {
            const int h = w;
            const __nv_bfloat16* Qh = sQ  + h*1152;
            const __nv_bfloat16* Kh = sK  + h*1152;
            const __nv_bfloat16* Vh = sVT + h*1152;

            #pragma unroll
            for (int pass = 0; pass < 2; pass++) {
                // QK^T scores for m-tiles {2*pass, 2*pass+1}, all 8 n-tiles
                float s[2][8][4];
                unsigned qa[2][4];
                #pragma unroll
                for (int mi = 0; mi < 2; mi++) {
                    const __nv_bfloat16* qp = Qh + ((pass*2+mi)*16 + g)*18;
                    qa[mi][0] = *reinterpret_cast<const unsigned*>(qp + 2*tq);
                    qa[mi][1] = *reinterpret_cast<const unsigned*>(qp + 8*18 + 2*tq);
                    qa[mi][2] = *reinterpret_cast<const unsigned*>(qp + 2*tq + 8);
                    qa[mi][3] = *reinterpret_cast<const unsigned*>(qp + 8*18 + 2*tq + 8);
                }
                #pragma unroll
                for (int nt = 0; nt < 8; nt++) {
                    const __nv_bfloat16* kp = Kh + (nt*8 + g)*18;
                    unsigned b0 = *reinterpret_cast<const unsigned*>(kp + 2*tq);
                    unsigned b1 = *reinterpret_cast<const unsigned*>(kp + 2*tq + 8);
                    #pragma unroll
                    for (int mi = 0; mi < 2; mi++) {
                        #pragma unroll
                        for (int e = 0; e < 4; e++) s[mi][nt][e] = 0.f;
                        mma_bf16(s[mi][nt], qa[mi], b0, b1);
                    }
                }
                // softmax per row (rowA = g, rowB = g+8 of each m-tile)
                float invA[2], invB[2];
                #pragma unroll
                for (int mi = 0; mi < 2; mi++) {
                    float mA = -1e30f, mB = -1e30f;
                    #pragma unroll
                    for (int nt = 0; nt < 8; nt++) {
                        mA = fmaxf(mA, fmaxf(s[mi][nt][0], s[mi][nt][1]));
                        mB = fmaxf(mB, fmaxf(s[mi][nt][2], s[mi][nt][3]));
                    }
                    mA = fmaxf(mA, __shfl_xor_sync(0xffffffffu, mA, 1));
                    mA = fmaxf(mA, __shfl_xor_sync(0xffffffffu, mA, 2));
                    mB = fmaxf(mB, __shfl_xor_sync(0xffffffffu, mB, 1));
                    mB = fmaxf(mB, __shfl_xor_sync(0xffffffffu, mB, 2));
                    float sA = 0.f, sB = 0.f;
                    #pragma unroll
                    for (int nt = 0; nt < 8; nt++) {
                        float e0 = __expf(s[mi][nt][0] - mA);
                        float e1 = __expf(s[mi][nt][1] - mA);
                        float e2 = __expf(s[mi][nt][2] - mB);
                        float e3 = __expf(s[mi][nt][3] - mB);
                        s[mi][nt][0]=e0; s[mi][nt][1]=e1; s[mi][nt][2]=e2; s[mi][nt][3]=e3;
                        sA += e0 + e1; sB += e2 + e3;
                    }
                    sA += __shfl_xor_sync(0xffffffffu, sA, 1);
                    sA += __shfl_xor_sync(0xffffffffu, sA, 2);
                    sB += __shfl_xor_sync(0xffffffffu, sB, 1);
                    sB += __shfl_xor_sync(0xffffffffu, sB, 2);
                    invA[mi] = 1.0f / sA;
                    invB[mi] = 1.0f / sB;
                }
                // PV: P fragments come straight from score fragments
                float o[2][2][4];
                #pragma unroll
                for (int mi = 0; mi < 2; mi++)
                    #pragma unroll
                    for (int nt2 = 0; nt2 < 2; nt2++)
                        #pragma unroll
                        for (int e = 0; e < 4; e++) o[mi][nt2][e] = 0.f;
                #pragma unroll
                for (int ks = 0; ks < 4; ks++) {
                    unsigned pa[2][4];
                    #pragma unroll
                    for (int mi = 0; mi < 2; mi++) {
                        pa[mi][0] = pack2(s[mi][2*ks  ][0], s[mi][2*ks  ][1]);
                        pa[mi][1] = pack2(s[mi][2*ks  ][2], s[mi][2*ks  ][3]);
                        pa[mi][2] = pack2(s[mi][2*ks+1][0], s[mi][2*ks+1][1]);
                        pa[mi][3] = pack2(s[mi][2*ks+1][2], s[mi][2*ks+1][3]);
                    }
                    #pragma unroll
                    for (int nt2 = 0; nt2 < 2; nt2++) {
                        const __nv_bfloat16* vp = Vh + (nt2*8 + g)*72 + ks*16;
                        unsigned b0 = *reinterpret_cast<const unsigned*>(vp + 2*tq);
                        unsigned b1 = *reinterpret_cast<const unsigned*>(vp + 2*tq + 8);
                        mma_bf16(o[0][nt2], pa[0], b0, b1);
                        mma_bf16(o[1][nt2], pa[1], b0, b1);
                    }
                }
                // store O (normalized) into sO as bf16 A-panel for proj
                #pragma unroll
                for (int mi = 0; mi < 2; mi++) {
                    const int row = (pass*2+mi)*16 + g;
                    #pragma unroll
                    for (int nt2 = 0; nt2 < 2; nt2++) {
                        const int dh = nt2*8 + 2*tq;
                        if (dh < 10) {
                            *reinterpret_cast<unsigned*>(sO + row*88 + h*10 + dh) =
                                pack2(o[mi][nt2][0]*invA[mi], o[mi][nt2][1]*invA[mi]);
                            *reinterpret_cast<unsigned*>(sO + (row+8)*88 + h*10 + dh) =
                                pack2(o[mi][nt2][2]*invB[mi], o[mi][nt2][3]*invB[mi]);
                        }
                    }
                }
            }
        }
        __syncthreads();

        // ---- proj GEMM [64x80]@[80x80] + bias + residual into sXN ----
        {
            const int mt = w >> 1;
            const int nb = (w & 1) * 5;
            float acc[5][4];
            #pragma unroll
            for (int j = 0; j < 5; j++)
                #pragma unroll
                for (int e = 0; e < 4; e++) acc[j][e] = 0.f;
            #pragma unroll
            for (int ks = 0; ks < 5; ks++) {
                unsigned a[4];
                const __nv_bfloat16* ap = sO + (mt*16 + g)*88 + ks*16;
                a[0] = *reinterpret_cast<const unsigned*>(ap + 2*tq);
                a[1] = *reinterpret_cast<const unsigned*>(ap + 8*88 + 2*tq);
                a[2] = *reinterpret_cast<const unsigned*>(ap + 2*tq + 8);
                a[3] = *reinterpret_cast<const unsigned*>(ap + 8*88 + 2*tq + 8);
                #pragma unroll
                for (int j = 0; j < 5; j++) {
                    const __nv_bfloat16* bp = sWprojT + ((nb+j)*8 + g)*88 + ks*16;
                    unsigned b0 = *reinterpret_cast<const unsigned*>(bp + 2*tq);
                    unsigned b1 = *reinterpret_cast<const unsigned*>(bp + 2*tq + 8);
                    mma_bf16(acc[j], a, b0, b1);
                }
            }
            const int rowA = mt*16 + g;
            #pragma unroll
            for (int j = 0; j < 5; j++) {
                const int c = (nb+j)*8 + 2*tq;
                sXN[rowA*81 + c]         += acc[j][0] + sBproj[c];
                sXN[rowA*81 + c + 1]     += acc[j][1] + sBproj[c+1];
                sXN[(rowA+8)*81 + c]     += acc[j][2] + sBproj[c];
                sXN[(rowA+8)*81 + c + 1] += acc[j][3] + sBproj[c+1];
            }
        }
        __syncthreads();

        // ---- coalesced store ----
        {
            const int t = tid >> 2, lg = tid & 3;
            const int ti = t >> 3, tj = t & 7;
            int pr, pc;
            if (IS_GRID) { pr = ti*16 + wh; pc = tj*16 + ww; }
            else         { pr = wh*8 + ti;  pc = ww*8 + tj;  }
            const long pix = ((long)bb*128 + pr)*128 + pc;
            float4* yr = reinterpret_cast<float4*>(y + pix*80) + lg*5;
            #pragma unroll
            for (int u = 0; u < 5; u++) {
                float4 f;
                f.x = sXN[t*81 + lg*20 + 4*u + 0];
                f.y = sXN[t*81 + lg*20 + 4*u + 1];
                f.z = sXN[t*81 + lg*20 + 4*u + 2];
                f.w = sXN[t*81 + lg*20 + 4*u + 3];
                yr[u] = f;
            }
        }
        __syncthreads();   // before next tile overwrites sXN/sXNh/sQ/sK/sVT/sO
    }
}

// =====================================================================
// Fused MLP via bf16 mma (unchanged from passing R3): 382us/launch
// =====================================================================
constexpr int MLP_SMEM_BYTES = 188032;
constexpr int MLP_TILES_PER_CTA = 4;
constexpr int MLP_NCTA = (TOK_TOTAL/64) / MLP_TILES_PER_CTA;  // 2048

template<bool RELU2>
__global__ void __launch_bounds__(256, 1)
mlp_kernel(const float* __restrict__ xin, float* __restrict__ xout,
           const float* __restrict__ w1, const float* __restrict__ w2,
           const float* __restrict__ b2, const float* __restrict__ gamma)
{
    extern __shared__ float smf[];
    char* smb = reinterpret_cast<char*>(smf);
    __nv_bfloat16* sW1T = reinterpret_cast<__nv_bfloat16*>(smb);            // [n=320][k=88]
    __nv_bfloat16* sW2T = reinterpret_cast<__nv_bfloat16*>(smb + 56320);    // [n=80][k=344]
    float*         sXN  = reinterpret_cast<float*>(smb + 111360);           // [64][81]
    __nv_bfloat16* sXNh = reinterpret_cast<__nv_bfloat16*>(smb + 132096);   // [64][88]
    __nv_bfloat16* sH   = reinterpret_cast<__nv_bfloat16*>(smb + 143360);   // [64][344]
    float*         sOut = reinterpret_cast<float*>(smb + 143360);           // alias
    float*         sB2  = reinterpret_cast<float*>(smb + 187392);
    float*         sG   = reinterpret_cast<float*>(smb + 187712);

    const int tid = threadIdx.x;

    for (int idx = tid; idx < 25600; idx += 256) {
        { int k = idx / 320, n = idx % 320; sW1T[n*88  + k] = __float2bfloat16(w1[idx]); }
        { int k = idx / 80,  n = idx % 80;  sW2T[n*344 + k] = __float2bfloat16(w2[idx]); }
    }
    if (tid < 80) { sB2[tid] = b2[tid]; sG[tid] = gamma[tid]; }

    const int w    = tid >> 5, lane = tid & 31;
    const int g    = lane >> 2, tq  = lane & 3;

    for (int it = 0; it < MLP_TILES_PER_CTA; it++) {
        const long tokBase = ((long)blockIdx.x * MLP_TILES_PER_CTA + it) * 64;

        {
            const int t = tid >> 2, lg = tid & 3;
            const float4* xr = reinterpret_cast<const float4*>(xin + (tokBase + t)*80) + lg*5;
            float v[20]; float ssq = 0.f;
            #pragma unroll
            for (int u = 0; u < 5; u++) {
                float4 f = xr[u];
                v[4*u]=f.x; v[4*u+1]=f.y; v[4*u+2]=f.z; v[4*u+3]=f.w;
                ssq += f.x*f.x + f.y*f.y + f.z*f.z + f.w*f.w;
            }
            ssq += __shfl_xor_sync(0xffffffffu, ssq, 1);
            ssq += __shfl_xor_sync(0xffffffffu, ssq, 2);
            const float inv = rsqrtf(fmaxf(ssq, 1e-24f));
            float* xn = sXN + t*81 + lg*20;
            unsigned* xh = reinterpret_cast<unsigned*>(sXNh + t*88 + lg*20);
            #pragma unroll
            for (int u = 0; u < 20; u++) { v[u] *= inv; xn[u] = v[u]; }
            #pragma unroll
            for (int u = 0; u < 10; u++) xh[u] = pack2(v[2*u], v[2*u+1]);
        }
        __syncthreads();

        {
            const int mt0   = (w & 1) * 2;
            const int nbase = (w >> 1) * 10;
            float acc[2][10][4];
            #pragma unroll
            for (int mi = 0; mi < 2; mi++)
                #pragma unroll
                for (int j = 0; j < 10; j++)
                    #pragma unroll
                    for (int e = 0; e < 4; e++) acc[mi][j][e] = 0.f;

            #pragma unroll
            for (int ks = 0; ks < 5; ks++) {
                unsigned a[2][4];
                #pragma unroll
                for (int mi = 0; mi < 2; mi++) {
                    const __nv_bfloat16* ap = sXNh + ((mt0+mi)*16 + g)*88 + ks*16;
                    a[mi][0] = *reinterpret_cast<const unsigned*>(ap + 2*tq);
                    a[mi][1] = *reinterpret_cast<const unsigned*>(ap + 8*88 + 2*tq);
                    a[mi][2] = *reinterpret_cast<const unsigned*>(ap + 8 + 2*tq);
                    a[mi][3] = *reinterpret_cast<const unsigned*>(ap + 8*88 + 8 + 2*tq);
                }
                #pragma unroll
                for (int j = 0; j < 10; j++) {
                    const __nv_bfloat16* bp = sW1T + ((nbase+j)*8 + g)*88 + ks*16;
                    unsigned b0 = *reinterpret_cast<const unsigned*>(bp + 2*tq);
                    unsigned b1 = *reinterpret_cast<const unsigned*>(bp + 8 + 2*tq);
                    mma_bf16(acc[0][j], a[0], b0, b1);
                    mma_bf16(acc[1][j], a[1], b0, b1);
                }
            }
            #pragma unroll
            for (int mi = 0; mi < 2; mi++) {
                const int r0 = (mt0+mi)*16 + g;
                #pragma unroll
                for (int j = 0; j < 10; j++) {
                    const int c = (nbase+j)*8 + 2*tq;
                    *reinterpret_cast<unsigned*>(sH + r0*344 + c) =
                        pack2(fmaxf(acc[mi][j][0], 0.f), fmaxf(acc[mi][j][1], 0.f));
                    *reinterpret_cast<unsigned*>(sH + (r0+8)*344 + c) =
                        pack2(fmaxf(acc[mi][j][2], 0.f), fmaxf(acc[mi][j][3], 0.f));
                }
            }
        }
        __syncthreads();

        {
            const int mt = w & 3;
            const int nb = (w >> 2) * 5;
            float acc2[5][4];
            #pragma unroll
            for (int j = 0; j < 5; j++)
                #pragma unroll
                for (int e = 0; e < 4; e++) acc2[j][e] = 0.f;

            #pragma unroll
            for (int ks = 0; ks < 20; ks++) {
                unsigned a[4];
                const __nv_bfloat16* ap = sH + (mt*16 + g)*344 + ks*16;
                a[0] = *reinterpret_cast<const unsigned*>(ap + 2*tq);
                a[1] = *reinterpret_cast<const unsigned*>(ap + 8*344 + 2*tq);
                a[2] = *reinterpret_cast<const unsigned*>(ap + 8 + 2*tq);
                a[3] = *reinterpret_cast<const unsigned*>(ap + 8*344 + 8 + 2*tq);
                #pragma unroll
                for (int j = 0; j < 5; j++) {
                    const __nv_bfloat16* bp = sW2T + ((nb+j)*8 + g)*344 + ks*16;
                    unsigned b0 = *reinterpret_cast<const unsigned*>(bp + 2*tq);
                    unsigned b1 = *reinterpret_cast<const unsigned*>(bp + 8 + 2*tq);
                    mma_bf16(acc2[j], a, b0, b1);
                }
            }
            __syncthreads();
            const int r0 = mt*16 + g;
            #pragma unroll
            for (int j = 0; j < 5; j++) {
                const int c = (nb+j)*8 + 2*tq;
                sOut[r0*81 + c]       = acc2[j][0];
                sOut[r0*81 + c + 1]   = acc2[j][1];
                sOut[(r0+8)*81 + c]     = acc2[j][2];
                sOut[(r0+8)*81 + c + 1] = acc2[j][3];
            }
        }
        __syncthreads();

        {
            const int t = tid >> 2, lg = tid & 3;
            float4* yr = reinterpret_cast<float4*>(xout + (tokBase + t)*80) + lg*5;
            #pragma unroll
            for (int u = 0; u < 5; u++) {
                float f[4];
                #pragma unroll
                for (int e = 0; e < 4; e++) {
                    const int idx = lg*20 + 4*u + e;
                    float hv = sOut[t*81 + idx] + sB2[idx];
                    if (RELU2) hv = fmaxf(hv, 0.f);
                    f[e] = sXN[t*81 + idx] + hv * sG[idx];
                }
                yr[u] = make_float4(f[0], f[1], f[2], f[3]);
            }
        }
        __syncthreads();
    }
}

// =====================================================================
extern "C" void kernel_launch(void* const* d_in, const int* in_sizes, int n_in,
                              void* d_out, int out_size)
{
    const float* x       = (const float*)d_in[0];
    const float* bw_qkv  = (const float*)d_in[1];
    const float* bb_qkv  = (const float*)d_in[2];
    const float* bw_proj = (const float*)d_in[3];
    const float* bb_proj = (const float*)d_in[4];
    const float* b_gamma = (const float*)d_in[5];
    const float* bw_mlp1 = (const float*)d_in[6];
    const float* bw_mlp2 = (const float*)d_in[7];
    const float* bb_mlp2 = (const float*)d_in[8];
    const float* gw_qkv  = (const float*)d_in[9];
    const float* gb_qkv  = (const float*)d_in[10];
    const float* gw_proj = (const float*)d_in[11];
    const float* gb_proj = (const float*)d_in[12];
    const float* g_gamma = (const float*)d_in[13];
    const float* gw_mlp1 = (const float*)d_in[14];
    const float* gw_mlp2 = (const float*)d_in[15];
    const float* gb_mlp2 = (const float*)d_in[16];
    float* out = (float*)d_out;

    float *buf1 = nullptr, *buf2 = nullptr;
    cudaGetSymbolAddress((void**)&buf1, g_buf1);
    cudaGetSymbolAddress((void**)&buf2, g_buf2);

    const size_t smA = ATTN_SMEM_BYTES;   // 156,160 B
    const size_t smM = MLP_SMEM_BYTES;    // 188,032 B
    cudaFuncSetAttribute(attn_kernel<false>, cudaFuncAttributeMaxDynamicSharedMemorySize, (int)smA);
    cudaFuncSetAttribute(attn_kernel<true>,  cudaFuncAttributeMaxDynamicSharedMemorySize, (int)smA);
    cudaFuncSetAttribute(mlp_kernel<true>,   cudaFuncAttributeMaxDynamicSharedMemorySize, (int)smM);
    cudaFuncSetAttribute(mlp_kernel<false>,  cudaFuncAttributeMaxDynamicSharedMemorySize, (int)smM);

    // stage 1: block SA
    attn_kernel<false><<<ATTN_NCTA, 256, smA>>>(x,    buf1, bw_qkv, bb_qkv, bw_proj, bb_proj);
    mlp_kernel<true>  <<<MLP_NCTA,  256, smM>>>(buf1, buf2, bw_mlp1, bw_mlp2, bb_mlp2, b_gamma);
    // stage 2: grid SA
    attn_kernel<true> <<<ATTN_NCTA, 256, smA>>>(buf2, buf1, gw_qkv, gb_qkv, gw_proj, gb_proj);
    mlp_kernel<false> <<<MLP_NCTA,  256, smM>>>(buf1, out, gw_mlp1, gw_mlp2, gb_mlp2, g_gamma);
}